// round 2
// baseline (speedup 1.0000x reference)
#include <cuda_runtime.h>

// Problem dims (fixed): B=8, N=1024, C=256, H=4, D=64
#define Bb   8
#define Nn   1024
#define Cc   256
#define Hh   4
#define Dd   64
#define HD   256               // H*D
#define ROWS (Bb * Nn)         // 8192
#define NEG_SLOPE 0.2f

// Scratch (device globals: allocation-free rule)
__device__ float g_Wx[ROWS * HD];   // 8 MB
__device__ float g_ei[ROWS * Hh];
__device__ float g_ej[ROWS * Hh];

// ---------------------------------------------------------------------------
// Kernel 1: Wx = x @ W   (8192x256 @ 256x256), 64x64 tiles, 4x4 per thread
// ---------------------------------------------------------------------------
__global__ void __launch_bounds__(256) gemm_k(const float* __restrict__ A,
                                              const float* __restrict__ Bm) {
    __shared__ float As[64][17];
    __shared__ float Bs[16][64];

    const int tid = threadIdx.x;
    const int tx = tid & 15;        // 0..15 -> 4 cols each
    const int ty = tid >> 4;        // 0..15 -> 4 rows each
    const int row0 = blockIdx.x * 64;
    const int col0 = blockIdx.y * 64;

    float acc[4][4] = {};

    const int ar = tid >> 2;              // 0..63
    const int akc = (tid & 3) * 4;        // 0,4,8,12
    const int br = tid >> 4;              // 0..15
    const int bc = (tid & 15) * 4;        // 0..60

    for (int k0 = 0; k0 < Cc; k0 += 16) {
        float4 av = *(const float4*)&A[(size_t)(row0 + ar) * Cc + k0 + akc];
        As[ar][akc + 0] = av.x;
        As[ar][akc + 1] = av.y;
        As[ar][akc + 2] = av.z;
        As[ar][akc + 3] = av.w;
        float4 bv = *(const float4*)&Bm[(size_t)(k0 + br) * HD + col0 + bc];
        *(float4*)&Bs[br][bc] = bv;
        __syncthreads();

#pragma unroll
        for (int kk = 0; kk < 16; kk++) {
            float ar4[4], br4[4];
#pragma unroll
            for (int i = 0; i < 4; i++) ar4[i] = As[ty * 4 + i][kk];
            float4 b4 = *(float4*)&Bs[kk][tx * 4];
            br4[0] = b4.x; br4[1] = b4.y; br4[2] = b4.z; br4[3] = b4.w;
#pragma unroll
            for (int i = 0; i < 4; i++)
#pragma unroll
                for (int j = 0; j < 4; j++)
                    acc[i][j] = fmaf(ar4[i], br4[j], acc[i][j]);
        }
        __syncthreads();
    }

#pragma unroll
    for (int i = 0; i < 4; i++) {
        float4 o = make_float4(acc[i][0], acc[i][1], acc[i][2], acc[i][3]);
        *(float4*)&g_Wx[(size_t)(row0 + ty * 4 + i) * HD + col0 + tx * 4] = o;
    }
}

// ---------------------------------------------------------------------------
// Kernel 2: e_i[b,n,h] = Wx[b,n,h,:].a_i[h],  e_j likewise.  1 block per row.
// ---------------------------------------------------------------------------
__global__ void __launch_bounds__(256) eij_k(const float* __restrict__ a) {
    __shared__ float s_a[2 * HD];   // a: (1,4,128) -> 512 floats
    __shared__ float s_pi[8], s_pj[8];

    const int tid = threadIdx.x;
    const int row = blockIdx.x;

    s_a[tid] = a[tid];
    s_a[tid + 256] = a[tid + 256];
    __syncthreads();

    const int h = tid >> 6;
    const int d = tid & 63;
    float v = g_Wx[(size_t)row * HD + tid];
    float pi = v * s_a[h * 128 + d];
    float pj = v * s_a[h * 128 + 64 + d];

    // warp reduce (64 threads per head == warps 2h, 2h+1)
#pragma unroll
    for (int off = 16; off > 0; off >>= 1) {
        pi += __shfl_down_sync(0xffffffffu, pi, off);
        pj += __shfl_down_sync(0xffffffffu, pj, off);
    }
    const int warp = tid >> 5;
    const int lane = tid & 31;
    if (lane == 0) { s_pi[warp] = pi; s_pj[warp] = pj; }
    __syncthreads();
    if (tid < Hh) {
        g_ei[row * Hh + tid] = s_pi[2 * tid] + s_pi[2 * tid + 1];
        g_ej[row * Hh + tid] = s_pj[2 * tid] + s_pj[2 * tid + 1];
    }
}

// ---------------------------------------------------------------------------
// Kernel 3: sparse masked softmax + gather-accumulate.  1 block per (b,n).
// ---------------------------------------------------------------------------
__global__ void __launch_bounds__(256) attn_k(const float* __restrict__ adj,
                                              float* __restrict__ out) {
    __shared__ int   s_idx[Nn];          // neighbor indices (compacted, sorted)
    __shared__ float s_w[Nn * Hh];       // [k][h] scores -> weights
    __shared__ float s_red[Hh][256];     // reductions
    __shared__ int   s_wcnt[8], s_woff[8];
    __shared__ int   s_cnt;

    const int tid  = threadIdx.x;
    const int blk  = blockIdx.x;          // b*N + n
    const int b    = blk >> 10;
    const int n    = blk & 1023;
    const int warp = tid >> 5;
    const int lane = tid & 31;

    if (tid == 0) s_cnt = 0;
    __syncthreads();

    // ---- deterministic ordered compaction of nonzero adj row (+ self) ----
    const float* arow = adj + (size_t)blk * Nn;
#pragma unroll
    for (int base = 0; base < Nn; base += 256) {
        int j = base + tid;
        bool p = (arow[j] != 0.0f) || (j == n);   // adj + I
        unsigned bal = __ballot_sync(0xffffffffu, p);
        int pre = __popc(bal & ((1u << lane) - 1u));
        if (lane == 0) s_wcnt[warp] = __popc(bal);
        __syncthreads();
        if (tid == 0) {
            int run = s_cnt;
#pragma unroll
            for (int w = 0; w < 8; w++) { s_woff[w] = run; run += s_wcnt[w]; }
            s_cnt = run;
        }
        __syncthreads();
        if (p) s_idx[s_woff[warp] + pre] = j;
        __syncthreads();
    }
    const int K = s_cnt;

    // ---- scores s = lrelu(e_i + e_j), find per-head max ----
    float4 eiv = *(const float4*)&g_ei[blk * Hh];
    float ei[4] = { eiv.x, eiv.y, eiv.z, eiv.w };
    float lmax[4] = { -1e30f, -1e30f, -1e30f, -1e30f };
    for (int k = tid; k < K; k += 256) {
        int j = s_idx[k];
        float4 ejv = *(const float4*)&g_ej[(b * Nn + j) * Hh];
        float ej[4] = { ejv.x, ejv.y, ejv.z, ejv.w };
#pragma unroll
        for (int h = 0; h < 4; h++) {
            float s = ei[h] + ej[h];
            s = s > 0.0f ? s : NEG_SLOPE * s;
            s_w[k * Hh + h] = s;
            lmax[h] = fmaxf(lmax[h], s);
        }
    }
#pragma unroll
    for (int h = 0; h < 4; h++) s_red[h][tid] = lmax[h];
    __syncthreads();
    for (int st = 128; st > 0; st >>= 1) {
        if (tid < st)
#pragma unroll
            for (int h = 0; h < 4; h++)
                s_red[h][tid] = fmaxf(s_red[h][tid], s_red[h][tid + st]);
        __syncthreads();
    }
    float m[4];
#pragma unroll
    for (int h = 0; h < 4; h++) m[h] = s_red[h][0];
    __syncthreads();

    // ---- exponentiate + per-head sum ----
    float lsum[4] = {};
    for (int k = tid; k < K; k += 256) {
#pragma unroll
        for (int h = 0; h < 4; h++) {
            float w = __expf(s_w[k * Hh + h] - m[h]);
            s_w[k * Hh + h] = w;
            lsum[h] += w;
        }
    }
#pragma unroll
    for (int h = 0; h < 4; h++) s_red[h][tid] = lsum[h];
    __syncthreads();
    for (int st = 128; st > 0; st >>= 1) {
        if (tid < st)
#pragma unroll
            for (int h = 0; h < 4; h++)
                s_red[h][tid] += s_red[h][tid + st];
        __syncthreads();
    }
    const int h = tid >> 6;
    const int d = tid & 63;
    float inv = 1.0f / s_red[h][0];
    __syncthreads();

    // ---- gather-accumulate: out[h,d] = sum_k w[k][h] * Wx[b, j_k, h, d] ----
    const float* wxb = g_Wx + (size_t)b * (Nn * HD) + h * Dd + d;
    float acc = 0.0f;
    int k = 0;
    for (; k + 4 <= K; k += 4) {
        int   j0 = s_idx[k],     j1 = s_idx[k + 1];
        int   j2 = s_idx[k + 2], j3 = s_idx[k + 3];
        float w0 = s_w[(k    ) * Hh + h], w1 = s_w[(k + 1) * Hh + h];
        float w2 = s_w[(k + 2) * Hh + h], w3 = s_w[(k + 3) * Hh + h];
        float v0 = __ldg(&wxb[(size_t)j0 * HD]);
        float v1 = __ldg(&wxb[(size_t)j1 * HD]);
        float v2 = __ldg(&wxb[(size_t)j2 * HD]);
        float v3 = __ldg(&wxb[(size_t)j3 * HD]);
        acc = fmaf(w0, v0, acc);
        acc = fmaf(w1, v1, acc);
        acc = fmaf(w2, v2, acc);
        acc = fmaf(w3, v3, acc);
    }
    for (; k < K; k++)
        acc = fmaf(s_w[k * Hh + h], __ldg(&wxb[(size_t)s_idx[k] * HD]), acc);

    out[(size_t)blk * HD + tid] = acc * inv;
}

// ---------------------------------------------------------------------------
extern "C" void kernel_launch(void* const* d_in, const int* in_sizes, int n_in,
                              void* d_out, int out_size) {
    // Identify inputs by element count (robust to ordering)
    const float *x = nullptr, *adj = nullptr, *W = nullptr, *a = nullptr;
    for (int i = 0; i < n_in; i++) {
        switch (in_sizes[i]) {
            case Bb * Nn * Cc:  x   = (const float*)d_in[i]; break;  // 2097152
            case Bb * Nn * Nn:  adj = (const float*)d_in[i]; break;  // 8388608
            case Cc * HD:       W   = (const float*)d_in[i]; break;  // 65536
            case Hh * 2 * Dd:   a   = (const float*)d_in[i]; break;  // 512
        }
    }
    float* out = (float*)d_out;

    dim3 ggrid(ROWS / 64, HD / 64);
    gemm_k<<<ggrid, 256>>>(x, W);
    eij_k<<<ROWS, 256>>>(a);
    attn_k<<<ROWS, 256>>>(adj, out);
}

// round 3
// speedup vs baseline: 1.1172x; 1.1172x over previous
#include <cuda_runtime.h>

// Problem dims (fixed): B=8, N=1024, C=256, H=4, D=64
#define Bb   8
#define Nn   1024
#define Cc   256
#define Hh   4
#define Dd   64
#define HD   256               // H*D
#define ROWS (Bb * Nn)         // 8192
#define NEG_SLOPE 0.2f

// Scratch (device globals: allocation-free rule)
__device__ float g_Wx[ROWS * HD];   // 8 MB
__device__ float g_ei[ROWS * Hh];
__device__ float g_ej[ROWS * Hh];

// ---------------------------------------------------------------------------
// Kernel 1: Wx = x @ W  (8192x256 @ 256x256), 128x64 tiles, 8x4 per thread,
// fused e_i/e_j epilogue (each 64-col tile == one head).
// ---------------------------------------------------------------------------
__global__ void __launch_bounds__(256) gemm_fused_k(const float* __restrict__ A,
                                                    const float* __restrict__ Bm,
                                                    const float* __restrict__ avec) {
    __shared__ float As[16][132];     // k-major, padded (132*4 % 16 == 0)
    __shared__ float Bs[16][68];
    __shared__ float s_ai[64], s_aj[64];

    const int tid = threadIdx.x;
    const int tx = tid & 15;          // 0..15 -> 4 cols each
    const int ty = tid >> 4;          // 0..15 -> 8 rows each
    const int row0 = blockIdx.x * 128;
    const int col0 = blockIdx.y * 64;
    const int h = blockIdx.y;         // head index (64 cols per head)

    if (tid < 64) {
        s_ai[tid] = avec[h * 128 + tid];
        s_aj[tid] = avec[h * 128 + 64 + tid];
    }

    float acc[8][4] = {};

    // A tile load: 128x16 floats = 256 thr * 2 float4.  ar=tid>>1, ac=(tid&1)*8
    const int ar = tid >> 1;
    const int ac = (tid & 1) * 8;
    // B tile load: 16x64 = 256 thr * 1 float4
    const int br = tid >> 4;
    const int bc = (tid & 15) * 4;

    for (int k0 = 0; k0 < Cc; k0 += 16) {
        float4 a0 = *(const float4*)&A[(size_t)(row0 + ar) * Cc + k0 + ac];
        float4 a1 = *(const float4*)&A[(size_t)(row0 + ar) * Cc + k0 + ac + 4];
        // transpose into k-major As
        As[ac + 0][ar] = a0.x; As[ac + 1][ar] = a0.y;
        As[ac + 2][ar] = a0.z; As[ac + 3][ar] = a0.w;
        As[ac + 4][ar] = a1.x; As[ac + 5][ar] = a1.y;
        As[ac + 6][ar] = a1.z; As[ac + 7][ar] = a1.w;
        *(float4*)&Bs[br][bc] = *(const float4*)&Bm[(size_t)(k0 + br) * HD + col0 + bc];
        __syncthreads();

#pragma unroll
        for (int kk = 0; kk < 16; kk++) {
            float4 av0 = *(float4*)&As[kk][ty * 8];
            float4 av1 = *(float4*)&As[kk][ty * 8 + 4];
            float4 bv  = *(float4*)&Bs[kk][tx * 4];
            float aa[8] = { av0.x, av0.y, av0.z, av0.w, av1.x, av1.y, av1.z, av1.w };
            float bb[4] = { bv.x, bv.y, bv.z, bv.w };
#pragma unroll
            for (int i = 0; i < 8; i++)
#pragma unroll
                for (int j = 0; j < 4; j++)
                    acc[i][j] = fmaf(aa[i], bb[j], acc[i][j]);
        }
        __syncthreads();
    }

    // Store Wx
#pragma unroll
    for (int i = 0; i < 8; i++) {
        float4 o = make_float4(acc[i][0], acc[i][1], acc[i][2], acc[i][3]);
        *(float4*)&g_Wx[(size_t)(row0 + ty * 8 + i) * HD + col0 + tx * 4] = o;
    }

    // Fused e_i / e_j epilogue: per-row dot with a_i[h], a_j[h] over this head's 64 cols
    float pi[8], pj[8];
#pragma unroll
    for (int i = 0; i < 8; i++) {
        float si = 0.0f, sj = 0.0f;
#pragma unroll
        for (int j = 0; j < 4; j++) {
            si = fmaf(acc[i][j], s_ai[tx * 4 + j], si);
            sj = fmaf(acc[i][j], s_aj[tx * 4 + j], sj);
        }
        pi[i] = si; pj[i] = sj;
    }
    // reduce across the 16 tx lanes (each 16-lane segment = one ty)
#pragma unroll
    for (int off = 8; off > 0; off >>= 1) {
#pragma unroll
        for (int i = 0; i < 8; i++) {
            pi[i] += __shfl_down_sync(0xffffffffu, pi[i], off, 16);
            pj[i] += __shfl_down_sync(0xffffffffu, pj[i], off, 16);
        }
    }
    if (tx == 0) {
#pragma unroll
        for (int i = 0; i < 8; i++) {
            int row = row0 + ty * 8 + i;
            g_ei[row * Hh + h] = pi[i];
            g_ej[row * Hh + h] = pj[i];
        }
    }
}

// ---------------------------------------------------------------------------
// Kernel 2: sparse masked softmax + gather-accumulate.  1 block per (b,n).
// ---------------------------------------------------------------------------
__global__ void __launch_bounds__(256) attn_k(const float* __restrict__ adj,
                                              float* __restrict__ out) {
    __shared__ int   s_idx[Nn];          // compacted neighbor indices (j-ordered)
    __shared__ float s_w[Nn * Hh];       // [k][h] scores -> weights
    __shared__ int   s_tot[8];
    __shared__ float s_rmax[8][4];
    __shared__ float s_rsum[8][4];

    const int tid  = threadIdx.x;
    const int blk  = blockIdx.x;          // b*N + n
    const int b    = blk >> 10;
    const int n    = blk & 1023;
    const int warp = tid >> 5;
    const int lane = tid & 31;

    // ---- compaction: each thread owns 4 consecutive j (j-ordered within warp segment) ----
    const float4* arow4 = (const float4*)(adj + (size_t)blk * Nn);
    float4 v = arow4[tid];
    const int j0 = tid * 4;
    unsigned mk = 0;
    if (v.x != 0.0f || j0     == n) mk |= 1u;
    if (v.y != 0.0f || j0 + 1 == n) mk |= 2u;
    if (v.z != 0.0f || j0 + 2 == n) mk |= 4u;
    if (v.w != 0.0f || j0 + 3 == n) mk |= 8u;
    int cnt = __popc(mk);
    // inclusive shfl scan over lanes
    int scan = cnt;
#pragma unroll
    for (int off = 1; off < 32; off <<= 1) {
        int t = __shfl_up_sync(0xffffffffu, scan, off);
        if (lane >= off) scan += t;
    }
    if (lane == 31) s_tot[warp] = scan;
    __syncthreads();
    int base = 0, K = 0;
#pragma unroll
    for (int w = 0; w < 8; w++) {
        int t = s_tot[w];
        if (w < warp) base += t;
        K += t;
    }
    int pos = base + (scan - cnt);
    if (mk & 1u) s_idx[pos++] = j0;
    if (mk & 2u) s_idx[pos++] = j0 + 1;
    if (mk & 4u) s_idx[pos++] = j0 + 2;
    if (mk & 8u) s_idx[pos++] = j0 + 3;
    __syncthreads();

    // ---- scores s = lrelu(e_i + e_j), per-head max ----
    float4 eiv = *(const float4*)&g_ei[blk * Hh];
    float ei[4] = { eiv.x, eiv.y, eiv.z, eiv.w };
    float lmax[4] = { -1e30f, -1e30f, -1e30f, -1e30f };
    for (int k = tid; k < K; k += 256) {
        float4 ejv = __ldg(&((const float4*)g_ej)[b * Nn + s_idx[k]]);
        float ej[4] = { ejv.x, ejv.y, ejv.z, ejv.w };
#pragma unroll
        for (int h = 0; h < 4; h++) {
            float s = ei[h] + ej[h];
            s = s > 0.0f ? s : NEG_SLOPE * s;
            s_w[k * Hh + h] = s;
            lmax[h] = fmaxf(lmax[h], s);
        }
    }
#pragma unroll
    for (int off = 16; off > 0; off >>= 1)
#pragma unroll
        for (int h = 0; h < 4; h++)
            lmax[h] = fmaxf(lmax[h], __shfl_xor_sync(0xffffffffu, lmax[h], off));
    if (lane == 0)
#pragma unroll
        for (int h = 0; h < 4; h++) s_rmax[warp][h] = lmax[h];
    __syncthreads();
    float mx[4];
#pragma unroll
    for (int h = 0; h < 4; h++) {
        float m = s_rmax[0][h];
#pragma unroll
        for (int w = 1; w < 8; w++) m = fmaxf(m, s_rmax[w][h]);
        mx[h] = m;
    }

    // ---- exponentiate + per-head sum (each thread touches only its own k's) ----
    float lsum[4] = {};
    for (int k = tid; k < K; k += 256) {
#pragma unroll
        for (int h = 0; h < 4; h++) {
            float w = __expf(s_w[k * Hh + h] - mx[h]);
            s_w[k * Hh + h] = w;
            lsum[h] += w;
        }
    }
#pragma unroll
    for (int off = 16; off > 0; off >>= 1)
#pragma unroll
        for (int h = 0; h < 4; h++)
            lsum[h] += __shfl_xor_sync(0xffffffffu, lsum[h], off);
    if (lane == 0)
#pragma unroll
        for (int h = 0; h < 4; h++) s_rsum[warp][h] = lsum[h];
    __syncthreads();   // also orders s_w exp-writes before gather reads

    const int h = tid >> 6;
    const int d = tid & 63;
    float tot = 0.0f;
#pragma unroll
    for (int w = 0; w < 8; w++) tot += s_rsum[w][h];
    const float inv = 1.0f / tot;

    // ---- gather-accumulate: out[h,d] = sum_k w[k][h] * Wx[b, j_k, h, d] ----
    const float* wxb = g_Wx + (size_t)b * (Nn * HD) + h * Dd + d;
    float acc = 0.0f;
    int k = 0;
    for (; k + 8 <= K; k += 8) {
        float vq[8]; float wq[8];
#pragma unroll
        for (int q = 0; q < 8; q++) {
            int j = s_idx[k + q];
            wq[q] = s_w[(k + q) * Hh + h];
            vq[q] = __ldg(&wxb[(size_t)j * HD]);
        }
#pragma unroll
        for (int q = 0; q < 8; q++) acc = fmaf(wq[q], vq[q], acc);
    }
    for (; k < K; k++)
        acc = fmaf(s_w[k * Hh + h], __ldg(&wxb[(size_t)s_idx[k] * HD]), acc);

    out[(size_t)blk * HD + tid] = acc * inv;
}

// ---------------------------------------------------------------------------
extern "C" void kernel_launch(void* const* d_in, const int* in_sizes, int n_in,
                              void* d_out, int out_size) {
    const float *x = nullptr, *adj = nullptr, *W = nullptr, *a = nullptr;
    for (int i = 0; i < n_in; i++) {
        switch (in_sizes[i]) {
            case Bb * Nn * Cc:  x   = (const float*)d_in[i]; break;  // 2097152
            case Bb * Nn * Nn:  adj = (const float*)d_in[i]; break;  // 8388608
            case Cc * HD:       W   = (const float*)d_in[i]; break;  // 65536
            case Hh * 2 * Dd:   a   = (const float*)d_in[i]; break;  // 512
        }
    }
    float* out = (float*)d_out;

    dim3 ggrid(ROWS / 128, HD / 64);
    gemm_fused_k<<<ggrid, 256>>>(x, W, a);
    attn_k<<<ROWS, 256>>>(adj, out);
}

// round 6
// speedup vs baseline: 1.3808x; 1.2359x over previous
#include <cuda_runtime.h>

// Problem dims (fixed): B=8, N=1024, C=256, H=4, D=64
#define Bb   8
#define Nn   1024
#define Cc   256
#define Hh   4
#define Dd   64
#define HD   256               // H*D
#define ROWS (Bb * Nn)         // 8192
#define NEG_SLOPE 0.2f

// Scratch (device globals: allocation-free rule)
__device__ float g_Wx[ROWS * HD];   // 8 MB
__device__ float g_ei[ROWS * Hh];
__device__ float g_ej[ROWS * Hh];

// ---------------------------------------------------------------------------
// Kernel 1: Wx = x @ W  (8192x256 @ 256x256), 128x64 tiles, 8x4 per thread,
// software-pipelined global loads, fused e_i/e_j epilogue (1 head per col-tile)
// ---------------------------------------------------------------------------
__global__ void __launch_bounds__(256) gemm_fused_k(const float* __restrict__ A,
                                                    const float* __restrict__ Bm,
                                                    const float* __restrict__ avec) {
    __shared__ float As[16][132];     // k-major, padded
    __shared__ float Bs[16][68];
    __shared__ float s_ai[64], s_aj[64];

    const int tid = threadIdx.x;
    const int tx = tid & 15;          // 0..15 -> 4 cols each
    const int ty = tid >> 4;          // 0..15 -> 8 rows each
    const int row0 = blockIdx.x * 128;
    const int col0 = blockIdx.y * 64;
    const int h = blockIdx.y;         // head index

    if (tid < 64) {
        s_ai[tid] = avec[h * 128 + tid];
        s_aj[tid] = avec[h * 128 + 64 + tid];
    }

    float acc[8][4] = {};

    const int ar = tid >> 1;
    const int ac = (tid & 1) * 8;
    const int br = tid >> 4;
    const int bc = (tid & 15) * 4;

    const float* aptr = &A[(size_t)(row0 + ar) * Cc + ac];
    const float* bptr = &Bm[(size_t)br * HD + col0 + bc];

    // preload k0 = 0
    float4 a0 = *(const float4*)(aptr);
    float4 a1 = *(const float4*)(aptr + 4);
    float4 bv = *(const float4*)(bptr);

    for (int k0 = 0; k0 < Cc; k0 += 16) {
        As[ac + 0][ar] = a0.x; As[ac + 1][ar] = a0.y;
        As[ac + 2][ar] = a0.z; As[ac + 3][ar] = a0.w;
        As[ac + 4][ar] = a1.x; As[ac + 5][ar] = a1.y;
        As[ac + 6][ar] = a1.z; As[ac + 7][ar] = a1.w;
        *(float4*)&Bs[br][bc] = bv;
        __syncthreads();

        if (k0 + 16 < Cc) {    // prefetch next k-tile during compute
            a0 = *(const float4*)(aptr + k0 + 16);
            a1 = *(const float4*)(aptr + k0 + 20);
            bv = *(const float4*)(bptr + (size_t)(k0 + 16) * HD);
        }

#pragma unroll
        for (int kk = 0; kk < 16; kk++) {
            float4 av0 = *(float4*)&As[kk][ty * 8];
            float4 av1 = *(float4*)&As[kk][ty * 8 + 4];
            float4 bv4 = *(float4*)&Bs[kk][tx * 4];
            float aa[8] = { av0.x, av0.y, av0.z, av0.w, av1.x, av1.y, av1.z, av1.w };
            float bb[4] = { bv4.x, bv4.y, bv4.z, bv4.w };
#pragma unroll
            for (int i = 0; i < 8; i++)
#pragma unroll
                for (int j = 0; j < 4; j++)
                    acc[i][j] = fmaf(aa[i], bb[j], acc[i][j]);
        }
        __syncthreads();
    }

    // Store Wx
#pragma unroll
    for (int i = 0; i < 8; i++) {
        float4 o = make_float4(acc[i][0], acc[i][1], acc[i][2], acc[i][3]);
        *(float4*)&g_Wx[(size_t)(row0 + ty * 8 + i) * HD + col0 + tx * 4] = o;
    }

    // Fused e_i / e_j epilogue
    float pi[8], pj[8];
#pragma unroll
    for (int i = 0; i < 8; i++) {
        float si = 0.0f, sj = 0.0f;
#pragma unroll
        for (int j = 0; j < 4; j++) {
            si = fmaf(acc[i][j], s_ai[tx * 4 + j], si);
            sj = fmaf(acc[i][j], s_aj[tx * 4 + j], sj);
        }
        pi[i] = si; pj[i] = sj;
    }
#pragma unroll
    for (int off = 8; off > 0; off >>= 1) {
#pragma unroll
        for (int i = 0; i < 8; i++) {
            pi[i] += __shfl_down_sync(0xffffffffu, pi[i], off, 16);
            pj[i] += __shfl_down_sync(0xffffffffu, pj[i], off, 16);
        }
    }
    if (tx == 0) {
#pragma unroll
        for (int i = 0; i < 8; i++) {
            int row = row0 + ty * 8 + i;
            g_ei[row * Hh + h] = pi[i];
            g_ej[row * Hh + h] = pj[i];
        }
    }
}

// ---------------------------------------------------------------------------
// Kernel 2: sparse masked softmax + float4 gather-accumulate. 1 block per (b,n)
// ---------------------------------------------------------------------------
__global__ void __launch_bounds__(256) attn_k(const float* __restrict__ adj,
                                              float* __restrict__ out) {
    __shared__ int   s_idx[Nn];          // compacted neighbor indices (ordered)
    __shared__ float s_w[Nn * Hh];       // [k][h] scores -> weights (float4/k)
    __shared__ int   s_tot[8];
    __shared__ float s_rmax[8][4];
    __shared__ float s_rsum[8][4];
    __shared__ float s_acc[4][Hh * 64];  // [grp][pos*4] partial accumulators

    const int tid  = threadIdx.x;
    const int blk  = blockIdx.x;          // b*N + n
    const int b    = blk >> 10;
    const int n    = blk & 1023;
    const int warp = tid >> 5;
    const int lane = tid & 31;

    // ---- compaction: each thread owns 4 consecutive j ----
    const float4* arow4 = (const float4*)(adj + (size_t)blk * Nn);
    float4 v = arow4[tid];
    const int j0 = tid * 4;
    unsigned mk = 0;
    if (v.x != 0.0f || j0     == n) mk |= 1u;
    if (v.y != 0.0f || j0 + 1 == n) mk |= 2u;
    if (v.z != 0.0f || j0 + 2 == n) mk |= 4u;
    if (v.w != 0.0f || j0 + 3 == n) mk |= 8u;
    int cnt = __popc(mk);
    int scan = cnt;
#pragma unroll
    for (int off = 1; off < 32; off <<= 1) {
        int t = __shfl_up_sync(0xffffffffu, scan, off);
        if (lane >= off) scan += t;
    }
    if (lane == 31) s_tot[warp] = scan;
    __syncthreads();
    int base = 0, K = 0;
#pragma unroll
    for (int w = 0; w < 8; w++) {
        int t = s_tot[w];
        if (w < warp) base += t;
        K += t;
    }
    int pos0 = base + (scan - cnt);
    if (mk & 1u) s_idx[pos0++] = j0;
    if (mk & 2u) s_idx[pos0++] = j0 + 1;
    if (mk & 4u) s_idx[pos0++] = j0 + 2;
    if (mk & 8u) s_idx[pos0++] = j0 + 3;
    __syncthreads();

    // ---- scores s = lrelu(e_i + e_j), per-head max ----
    float4 eiv = *(const float4*)&g_ei[blk * Hh];
    float ei[4] = { eiv.x, eiv.y, eiv.z, eiv.w };
    float lmax[4] = { -1e30f, -1e30f, -1e30f, -1e30f };
    for (int k = tid; k < K; k += 256) {
        float4 ejv = __ldg(&((const float4*)g_ej)[b * Nn + s_idx[k]]);
        float s0 = ei[0] + ejv.x, s1 = ei[1] + ejv.y;
        float s2 = ei[2] + ejv.z, s3 = ei[3] + ejv.w;
        s0 = s0 > 0.0f ? s0 : NEG_SLOPE * s0;
        s1 = s1 > 0.0f ? s1 : NEG_SLOPE * s1;
        s2 = s2 > 0.0f ? s2 : NEG_SLOPE * s2;
        s3 = s3 > 0.0f ? s3 : NEG_SLOPE * s3;
        *(float4*)&s_w[k * Hh] = make_float4(s0, s1, s2, s3);
        lmax[0] = fmaxf(lmax[0], s0); lmax[1] = fmaxf(lmax[1], s1);
        lmax[2] = fmaxf(lmax[2], s2); lmax[3] = fmaxf(lmax[3], s3);
    }
#pragma unroll
    for (int off = 16; off > 0; off >>= 1)
#pragma unroll
        for (int h = 0; h < 4; h++)
            lmax[h] = fmaxf(lmax[h], __shfl_xor_sync(0xffffffffu, lmax[h], off));
    if (lane == 0)
#pragma unroll
        for (int h = 0; h < 4; h++) s_rmax[warp][h] = lmax[h];
    __syncthreads();
    float mx[4];
#pragma unroll
    for (int h = 0; h < 4; h++) {
        float m = s_rmax[0][h];
#pragma unroll
        for (int w = 1; w < 8; w++) m = fmaxf(m, s_rmax[w][h]);
        mx[h] = m;
    }

    // ---- exponentiate + per-head sum ----
    float lsum[4] = {};
    for (int k = tid; k < K; k += 256) {
        float4 sv = *(float4*)&s_w[k * Hh];
        sv.x = __expf(sv.x - mx[0]); sv.y = __expf(sv.y - mx[1]);
        sv.z = __expf(sv.z - mx[2]); sv.w = __expf(sv.w - mx[3]);
        *(float4*)&s_w[k * Hh] = sv;
        lsum[0] += sv.x; lsum[1] += sv.y; lsum[2] += sv.z; lsum[3] += sv.w;
    }
#pragma unroll
    for (int off = 16; off > 0; off >>= 1)
#pragma unroll
        for (int h = 0; h < 4; h++)
            lsum[h] += __shfl_xor_sync(0xffffffffu, lsum[h], off);
    if (lane == 0)
#pragma unroll
        for (int h = 0; h < 4; h++) s_rsum[warp][h] = lsum[h];
    __syncthreads();   // orders s_w exp-writes before gather reads

    // ---- float4 gather: pos owns out floats [4pos,4pos+4), grp splits k ----
    const int pos = tid & 63;
    const int grp = tid >> 6;
    const int hh  = pos >> 4;            // head of this float4
    const float4* wx4 = (const float4*)(g_Wx + (size_t)b * (Nn * HD));
    float4 acc = make_float4(0.f, 0.f, 0.f, 0.f);
    int k = grp;
    for (; k + 12 < K; k += 16) {
        int ja = s_idx[k], jb = s_idx[k + 4], jc = s_idx[k + 8], jd = s_idx[k + 12];
        float wa = s_w[(k     ) * Hh + hh], wb = s_w[(k +  4) * Hh + hh];
        float wc = s_w[(k +  8) * Hh + hh], wd = s_w[(k + 12) * Hh + hh];
        float4 va = __ldg(&wx4[(size_t)ja * 64 + pos]);
        float4 vb = __ldg(&wx4[(size_t)jb * 64 + pos]);
        float4 vc = __ldg(&wx4[(size_t)jc * 64 + pos]);
        float4 vd = __ldg(&wx4[(size_t)jd * 64 + pos]);
        acc.x = fmaf(wa, va.x, acc.x); acc.y = fmaf(wa, va.y, acc.y);
        acc.z = fmaf(wa, va.z, acc.z); acc.w = fmaf(wa, va.w, acc.w);
        acc.x = fmaf(wb, vb.x, acc.x); acc.y = fmaf(wb, vb.y, acc.y);
        acc.z = fmaf(wb, vb.z, acc.z); acc.w = fmaf(wb, vb.w, acc.w);
        acc.x = fmaf(wc, vc.x, acc.x); acc.y = fmaf(wc, vc.y, acc.y);
        acc.z = fmaf(wc, vc.z, acc.z); acc.w = fmaf(wc, vc.w, acc.w);
        acc.x = fmaf(wd, vd.x, acc.x); acc.y = fmaf(wd, vd.y, acc.y);
        acc.z = fmaf(wd, vd.z, acc.z); acc.w = fmaf(wd, vd.w, acc.w);
    }
    for (; k < K; k += 4) {
        int j = s_idx[k];
        float w = s_w[k * Hh + hh];
        float4 vv = __ldg(&wx4[(size_t)j * 64 + pos]);
        acc.x = fmaf(w, vv.x, acc.x); acc.y = fmaf(w, vv.y, acc.y);
        acc.z = fmaf(w, vv.z, acc.z); acc.w = fmaf(w, vv.w, acc.w);
    }
    *(float4*)&s_acc[grp][pos * 4] = acc;
    __syncthreads();

    // ---- cross-group reduce + normalize + store ----
    if (tid < 64) {
        const int h = tid >> 4;
        float4 r = *(float4*)&s_acc[0][tid * 4];
#pragma unroll
        for (int g = 1; g < 4; g++) {
            float4 t = *(float4*)&s_acc[g][tid * 4];
            r.x += t.x; r.y += t.y; r.z += t.z; r.w += t.w;
        }
        float tot = 0.0f;
#pragma unroll
        for (int w = 0; w < 8; w++) tot += s_rsum[w][h];
        float inv = 1.0f / tot;
        r.x *= inv; r.y *= inv; r.z *= inv; r.w *= inv;
        *(float4*)&out[(size_t)blk * HD + tid * 4] = r;
    }
}

// ---------------------------------------------------------------------------
extern "C" void kernel_launch(void* const* d_in, const int* in_sizes, int n_in,
                              void* d_out, int out_size) {
    const float *x = nullptr, *adj = nullptr, *W = nullptr, *a = nullptr;
    for (int i = 0; i < n_in; i++) {
        switch (in_sizes[i]) {
            case Bb * Nn * Cc:  x   = (const float*)d_in[i]; break;  // 2097152
            case Bb * Nn * Nn:  adj = (const float*)d_in[i]; break;  // 8388608
            case Cc * HD:       W   = (const float*)d_in[i]; break;  // 65536
            case Hh * 2 * Dd:   a   = (const float*)d_in[i]; break;  // 512
        }
    }
    float* out = (float*)d_out;

    dim3 ggrid(ROWS / 128, HD / 64);
    gemm_fused_k<<<ggrid, 256>>>(x, W, a);
    attn_k<<<ROWS, 256>>>(adj, out);
}